// round 16
// baseline (speedup 1.0000x reference)
#include <cuda_runtime.h>
#include <cstdint>
#include <cfloat>

#define EPSB 1e-5f
constexpr int Lc  = 32;
constexpr int Ec  = 1024;
constexpr int Vc  = 2048;
constexpr int Fc  = 8;
constexpr int NT  = Lc * Ec;            // 32768
constexpr int D0c = 512, D1Rc = 129, D1Ec = 640;
constexpr int SIGc = 584;               // 8 + 64 + 512
constexpr int NDIAG = Lc * Fc * 2;      // 512
constexpr int GEMM_BLKS = NT / 128;     // 256
constexpr float DT = 1.0f / 51360.0f;   // arange(320)/ (320*321/2)

// ---------------- static device scratch (no allocations) ----------------
__device__ float g_Z1[(size_t)Fc * NT * 128];     // 128 MB pre-BN layer-1 out
__device__ float g_Z2[(size_t)Fc * NT * 128];     // 128 MB pre-BN layer-2 out
__device__ float g_part[(size_t)Fc * GEMM_BLKS * 128 * 2];
__device__ float g_stats[2];
__device__ float g_alpha[Fc * 128], g_beta[Fc * 128];
__device__ float g_sc1[Fc * 128], g_sh1[Fc * 128];
__device__ float g_sc2[Fc * 128], g_sh2[Fc * 128];
__device__ float g_zout[(size_t)Fc * NT];
__device__ float g_zpart[Fc * 128 * 2];
__device__ float g_osc[Fc], g_osh[Fc];
__device__ float g_fv[(size_t)Lc * Fc * Vc];      // 2 MB filtration values
__device__ float g_sig[(size_t)NDIAG * SIGc];     // signatures

// ---------------- 1) batch mean/var of eigenvalues ----------------
__global__ void k_eigstats(const float* __restrict__ x) {
    __shared__ float ss[1024], sq[1024];
    int tid = threadIdx.x;
    float s = 0.f, q = 0.f;
    for (int i = tid; i < NT; i += 1024) { float v = x[i]; s += v; q += v * v; }
    ss[tid] = s; sq[tid] = q; __syncthreads();
    for (int o = 512; o; o >>= 1) {
        if (tid < o) { ss[tid] += ss[tid + o]; sq[tid] += sq[tid + o]; }
        __syncthreads();
    }
    if (tid == 0) {
        float m = ss[0] / (float)NT;
        g_stats[0] = m;
        g_stats[1] = sq[0] / (float)NT - m * m;
    }
}

// ---------------- 2) fold input Linear+BN into affine (bin cancels) ----------------
__global__ void k_l1prep(const float* __restrict__ Win, const float* __restrict__ gin,
                         const float* __restrict__ betain) {
    int tid = threadIdx.x;                     // f*128 + j
    float w   = Win[tid];
    float inv = rsqrtf(w * w * g_stats[1] + EPSB);
    float al  = w * inv * gin[tid];
    g_alpha[tid] = al;
    g_beta[tid]  = betain[tid] - g_stats[0] * al;
}

// ---------------- 3) hidden-layer SGEMM with fused input transform + stats ----------------
// layer 0: A[n][k] = relu(alpha[k]*x[n]+beta[k]);   dst g_Z1, weights Wh[f][0]
// layer 1: A[n][k] = relu(sc1[k]*Z1[n][k]+sh1[k]);  dst g_Z2, weights Wh[f][1]
__global__ void __launch_bounds__(256)
k_gemm(const float* __restrict__ x, const float* __restrict__ Wh,
       const float* __restrict__ bh, int layer)
{
    __shared__ __align__(16) float sA[16][132];
    __shared__ __align__(16) float sB[16][132];
    __shared__ float sX[128], sS[128], sH[128];

    int f = blockIdx.y, n0 = blockIdx.x * 128, tid = threadIdx.x;
    int tx = tid & 15, ty = tid >> 4;

    if (tid < 128) {
        if (layer == 0) {
            sS[tid] = g_alpha[f * 128 + tid];
            sH[tid] = g_beta [f * 128 + tid];
            sX[tid] = x[n0 + tid];
        } else {
            sS[tid] = g_sc1[f * 128 + tid];
            sH[tid] = g_sh1[f * 128 + tid];
        }
    }
    __syncthreads();

    const float* W    = Wh + (size_t)(f * 2 + layer) * (128 * 128); // [j][k]
    const float* Zsrc = g_Z1 + ((size_t)f * NT + n0) * 128;
    float*       Zdst = (layer == 0) ? g_Z1 : g_Z2;

    float acc[8][8];
#pragma unroll
    for (int i = 0; i < 8; i++)
#pragma unroll
        for (int j = 0; j < 8; j++) acc[i][j] = 0.f;

    for (int k0 = 0; k0 < 128; k0 += 16) {
#pragma unroll
        for (int it = 0; it < 8; it++) {
            int e = tid + it * 256;
            int r = e >> 4, kk = e & 15;
            float a;
            if (layer == 0) a = sS[k0 + kk] * sX[r] + sH[k0 + kk];
            else            a = sS[k0 + kk] * Zsrc[(size_t)r * 128 + k0 + kk] + sH[k0 + kk];
            sA[kk][r] = fmaxf(a, 0.f);
            sB[kk][r] = W[r * 128 + k0 + kk];
        }
        __syncthreads();
#pragma unroll
        for (int kk = 0; kk < 16; kk++) {
            float4 a0 = *(const float4*)&sA[kk][ty * 8];
            float4 a1 = *(const float4*)&sA[kk][ty * 8 + 4];
            float4 b0 = *(const float4*)&sB[kk][tx * 8];
            float4 b1 = *(const float4*)&sB[kk][tx * 8 + 4];
            float av[8] = {a0.x, a0.y, a0.z, a0.w, a1.x, a1.y, a1.z, a1.w};
            float bv[8] = {b0.x, b0.y, b0.z, b0.w, b1.x, b1.y, b1.z, b1.w};
#pragma unroll
            for (int i = 0; i < 8; i++)
#pragma unroll
                for (int j = 0; j < 8; j++) acc[i][j] = fmaf(av[i], bv[j], acc[i][j]);
        }
        __syncthreads();
    }

    // epilogue: +bias, store, per-column stats partials (deterministic)
    float bb[8], cs[8], cq[8];
#pragma unroll
    for (int j = 0; j < 8; j++) {
        bb[j] = bh[(f * 2 + layer) * 128 + tx * 8 + j];
        cs[j] = 0.f; cq[j] = 0.f;
    }
#pragma unroll
    for (int i = 0; i < 8; i++) {
        float v[8];
#pragma unroll
        for (int j = 0; j < 8; j++) {
            v[j] = acc[i][j] + bb[j];
            cs[j] += v[j]; cq[j] += v[j] * v[j];
        }
        float* zr = Zdst + ((size_t)f * NT + n0 + ty * 8 + i) * 128 + tx * 8;
        *(float4*)(zr)     = make_float4(v[0], v[1], v[2], v[3]);
        *(float4*)(zr + 4) = make_float4(v[4], v[5], v[6], v[7]);
    }
#pragma unroll
    for (int j = 0; j < 8; j++) { sA[ty][tx * 8 + j] = cs[j]; sB[ty][tx * 8 + j] = cq[j]; }
    __syncthreads();
    if (tid < 128) {
        float s = 0.f, q = 0.f;
#pragma unroll
        for (int t = 0; t < 16; t++) { s += sA[t][tid]; q += sB[t][tid]; }
        size_t pi = ((size_t)f * gridDim.x + blockIdx.x) * 128 + tid;
        g_part[2 * pi]     = s;
        g_part[2 * pi + 1] = q;
    }
}

// ---------------- 4) reduce per-block stats -> BN scale/shift ----------------
__global__ void k_colreduce(const float* __restrict__ gh, const float* __restrict__ beh,
                            int layer) {
    int tid = threadIdx.x;                     // 1024 = F*HU
    int f = tid >> 7, col = tid & 127;
    float s = 0.f, q = 0.f;
    for (int b = 0; b < GEMM_BLKS; b++) {
        size_t pi = ((size_t)f * GEMM_BLKS + b) * 128 + col;
        s += g_part[2 * pi];
        q += g_part[2 * pi + 1];
    }
    float mean = s / (float)NT;
    float var  = q / (float)NT - mean * mean;
    float sc = gh[(f * 2 + layer) * 128 + col] * rsqrtf(var + EPSB);
    float sh = beh[(f * 2 + layer) * 128 + col] - mean * sc;
    if (layer == 0) { g_sc1[tid] = sc; g_sh1[tid] = sh; }
    else            { g_sc2[tid] = sc; g_sh2[tid] = sh; }
}

// ---------------- 5) output layer: zout = relu(bn(Z2)) . Wout + bout; stats ----------------
__global__ void __launch_bounds__(256)
k_outlayer(const float* __restrict__ Wout, const float* __restrict__ bout)
{
    __shared__ float sWo[128], sSc[128], sSh[128];
    __shared__ float rs[8], rq[8];
    int f = blockIdx.y, tid = threadIdx.x;
    int warp = tid >> 5, lane = tid & 31;
    if (tid < 128) {
        sWo[tid] = Wout[f * 128 + tid];
        sSc[tid] = g_sc2[f * 128 + tid];
        sSh[tid] = g_sh2[f * 128 + tid];
    }
    __syncthreads();
    float bo = bout[f];
    float bs = 0.f, bq = 0.f;
    int rbase = blockIdx.x * 256 + warp * 32;
    for (int r = 0; r < 32; r++) {
        const float* zr = g_Z2 + ((size_t)f * NT + rbase + r) * 128;
        float acc = 0.f;
#pragma unroll
        for (int q4 = 0; q4 < 4; q4++) {
            int j = lane + q4 * 32;
            acc = fmaf(fmaxf(fmaf(sSc[j], zr[j], sSh[j]), 0.f), sWo[j], acc);
        }
#pragma unroll
        for (int o = 16; o; o >>= 1) acc += __shfl_xor_sync(0xffffffffu, acc, o);
        if (lane == 0) {
            acc += bo;
            g_zout[(size_t)f * NT + rbase + r] = acc;
            bs += acc; bq += acc * acc;
        }
    }
    if (lane == 0) { rs[warp] = bs; rq[warp] = bq; }
    __syncthreads();
    if (tid == 0) {
        float s = 0.f, q = 0.f;
#pragma unroll
        for (int w = 0; w < 8; w++) { s += rs[w]; q += rq[w]; }
        g_zpart[((size_t)f * 128 + blockIdx.x) * 2]     = s;
        g_zpart[((size_t)f * 128 + blockIdx.x) * 2 + 1] = q;
    }
}

__global__ void k_zreduce(const float* __restrict__ gout, const float* __restrict__ beout) {
    int tid = threadIdx.x;                     // 256 = 8 f * 32 lanes
    int f = tid >> 5, lane = tid & 31;
    float s = 0.f, q = 0.f;
    for (int b = lane; b < 128; b += 32) {
        s += g_zpart[((size_t)f * 128 + b) * 2];
        q += g_zpart[((size_t)f * 128 + b) * 2 + 1];
    }
#pragma unroll
    for (int o = 16; o; o >>= 1) {
        s += __shfl_xor_sync(0xffffffffu, s, o);
        q += __shfl_xor_sync(0xffffffffu, q, o);
    }
    if (lane == 0) {
        float mean = s / (float)NT;
        float var  = q / (float)NT - mean * mean;
        float osc  = gout[f] * rsqrtf(var + EPSB);
        g_osc[f] = osc;
        g_osh[f] = beout[f] - mean * osc;
    }
}

// ---------------- 6) einsum: fv[l,f,v] = sum_e relu(bn(zout))[f,l,e] * evsq[l,e,v] ----------------
__global__ void __launch_bounds__(256)
k_einsum(const float* __restrict__ evsq)
{
    __shared__ float sev[8][1024];
    int l = blockIdx.y, tid = threadIdx.x;
    for (int i = tid; i < 8 * 1024; i += 256) {
        int f = i >> 10, e = i & 1023;
        float z = g_zout[(size_t)f * NT + (size_t)l * Ec + e];
        sev[f][e] = fmaxf(fmaf(g_osc[f], z, g_osh[f]), 0.f);
    }
    __syncthreads();
    int vh = blockIdx.x * 256 + tid;           // float2 index
    const float2* w2 = (const float2*)evsq + (size_t)l * Ec * (Vc / 2) + vh;
    float2 acc[8];
#pragma unroll
    for (int f = 0; f < 8; f++) { acc[f].x = 0.f; acc[f].y = 0.f; }
#pragma unroll 4
    for (int e = 0; e < Ec; e++) {
        float2 w = w2[(size_t)e * (Vc / 2)];
#pragma unroll
        for (int f = 0; f < 8; f++) {
            float sv = sev[f][e];
            acc[f].x = fmaf(sv, w.x, acc[f].x);
            acc[f].y = fmaf(sv, w.y, acc[f].y);
        }
    }
#pragma unroll
    for (int f = 0; f < 8; f++)
        ((float2*)g_fv)[(size_t)(l * Fc + f) * (Vc / 2) + vh] = acc[f];
}

// ---------------- 7) per-diagram: gather -> project -> sort -> level-3 signature ----------------
__global__ void __launch_bounds__(512)
k_diagram(const int* __restrict__ dgm0, const int* __restrict__ dgm1rel,
          const int* __restrict__ dgm1ext,
          const float* __restrict__ Wp, const float* __restrict__ bp)
{
    __shared__ float s_vals[640];
    __shared__ float s_srt[7][513];
    __shared__ float s_dx[319][8];

    int diag = blockIdx.x;
    int row = diag >> 1, which = diag & 1;
    int tid = threadIdx.x;
    const float* fvr = g_fv + (size_t)row * Vc;

    if (which == 0) {
        const int* i0 = dgm0 + (size_t)row * D0c;
        const int* ir = dgm1rel + (size_t)row * D1Rc;
        s_vals[tid] = fvr[i0[tid]];
        if (tid < 128) s_vals[512 + tid] = fvr[ir[128 - tid]];   // rel[1:][::-1]
    } else {
        const int* ie = dgm1ext + (size_t)row * D1Ec;
        for (int i = tid; i < 640; i += 512) s_vals[i] = fvr[ie[i]];
    }
    for (int i = tid; i < 7 * 192; i += 512) {                   // pad [320,512) with +inf
        int s = i / 192, p = 320 + (i % 192);
        s_srt[s][p] = FLT_MAX;
    }
    __syncthreads();
    for (int i = tid; i < 7 * 320; i += 512) {                   // Conv1d(1,7,k=2,s=2)
        int s = i / 320, p = i % 320;
        s_srt[s][p] = s_vals[2 * p] * Wp[2 * s] + s_vals[2 * p + 1] * Wp[2 * s + 1] + bp[s];
    }
    // bitonic sort ascending, 7 rows x 512 in parallel
    for (int k = 2; k <= 512; k <<= 1) {
        for (int j = k >> 1; j > 0; j >>= 1) {
            __syncthreads();
            int i = tid, ixj = i ^ j;
            if (ixj > i) {
                bool up = ((i & k) == 0);
#pragma unroll
                for (int r = 0; r < 7; r++) {
                    float x0 = s_srt[r][i], x1 = s_srt[r][ixj];
                    if ((x0 > x1) == up) { s_srt[r][i] = x1; s_srt[r][ixj] = x0; }
                }
            }
        }
    }
    __syncthreads();
    for (int i = tid; i < 319 * 8; i += 512) {                   // path deltas
        int p = i >> 3, d = i & 7;
        s_dx[p][d] = (d == 0) ? DT : (s_srt[d - 1][p + 1] - s_srt[d - 1][p]);
    }
    __syncthreads();

    // Chen scan: thread (a,b,c) owns s3[a,b,c], keeps private s1[a], s2[a,b]
    int a = tid >> 6, b = (tid >> 3) & 7, c = tid & 7;
    float ta = s_dx[0][a], tb = s_dx[0][b], tc = s_dx[0][c];
    float s1 = ta;
    float s2 = 0.5f * ta * tb;
    float s3 = s2 * tc * (1.0f / 3.0f);
    for (int p = 1; p < 319; p++) {
        ta = s_dx[p][a]; tb = s_dx[p][b]; tc = s_dx[p][c];
        float hb = 0.5f * tb;
        float u  = ta * hb;                    // t2[a,b]
        float t2bc = hb * tc;                  // t2[b,c]
        float v  = fmaf(u, 1.0f / 3.0f, s2);   // t3/tc + s2
        s3 = fmaf(tc, v, s3);
        s3 = fmaf(s1, t2bc, s3);
        s2 = fmaf(s1, tb, s2 + u);
        s1 += ta;
    }
    float* o = g_sig + (size_t)diag * SIGc;
    o[72 + tid] = s3;
    if (c == 0) o[8 + (tid >> 3)] = s2;
    if ((tid & 63) == 0) o[a] = s1;
}

// ---------------- 8) final linear + BN over 32 ----------------
__global__ void __launch_bounds__(1024)
k_final(const float* __restrict__ Wf, const float* __restrict__ bf,
        const float* __restrict__ gf, const float* __restrict__ btf,
        float* __restrict__ out)
{
    __shared__ float s_o[32];
    int w = threadIdx.x >> 5, lane = threadIdx.x & 31;
    const float* xr = g_sig + (size_t)w * 9344;
    float acc = 0.f;
    for (int k = lane; k < 9344; k += 32) acc = fmaf(xr[k], Wf[k], acc);
#pragma unroll
    for (int o = 16; o; o >>= 1) acc += __shfl_xor_sync(0xffffffffu, acc, o);
    if (lane == 0) s_o[w] = acc + bf[0];
    __syncthreads();
    if (threadIdx.x < 32) {
        float v = s_o[threadIdx.x];
        float s = v, q = v * v;
#pragma unroll
        for (int o = 16; o; o >>= 1) {
            s += __shfl_xor_sync(0xffffffffu, s, o);
            q += __shfl_xor_sync(0xffffffffu, q, o);
        }
        float m = s * (1.0f / 32.0f);
        float var = q * (1.0f / 32.0f) - m * m;
        out[threadIdx.x] = (v - m) * rsqrtf(var + EPSB) * gf[0] + btf[0];
    }
}

extern "C" void kernel_launch(void* const* d_in, const int* in_sizes, int n_in,
                              void* d_out, int out_size) {
    const float* eig   = (const float*)d_in[0];
    const float* evsq  = (const float*)d_in[1];
    const int*   dgm0  = (const int*)d_in[2];
    const int*   d1rel = (const int*)d_in[3];
    const int*   d1ext = (const int*)d_in[4];
    const float* Win   = (const float*)d_in[5];
    // d_in[6] = mlp_bin: cancels exactly inside the folded input-layer BN
    const float* gin   = (const float*)d_in[7];
    const float* bein  = (const float*)d_in[8];
    const float* Wh    = (const float*)d_in[9];
    const float* bh    = (const float*)d_in[10];
    const float* gh    = (const float*)d_in[11];
    const float* beh   = (const float*)d_in[12];
    const float* Wout  = (const float*)d_in[13];
    const float* bout  = (const float*)d_in[14];
    const float* gout  = (const float*)d_in[15];
    const float* beout = (const float*)d_in[16];
    const float* Wp    = (const float*)d_in[17];
    const float* bp    = (const float*)d_in[18];
    const float* Wfin  = (const float*)d_in[19];
    const float* bfin  = (const float*)d_in[20];
    const float* gfin  = (const float*)d_in[21];
    const float* befin = (const float*)d_in[22];
    float* out = (float*)d_out;

    k_eigstats<<<1, 1024>>>(eig);
    k_l1prep<<<1, 1024>>>(Win, gin, bein);
    dim3 gg(GEMM_BLKS, Fc);
    k_gemm<<<gg, 256>>>(eig, Wh, bh, 0);
    k_colreduce<<<1, 1024>>>(gh, beh, 0);
    k_gemm<<<gg, 256>>>(eig, Wh, bh, 1);
    k_colreduce<<<1, 1024>>>(gh, beh, 1);
    k_outlayer<<<dim3(128, Fc), 256>>>(Wout, bout);
    k_zreduce<<<1, 256>>>(gout, beout);
    k_einsum<<<dim3(4, Lc), 256>>>(evsq);
    k_diagram<<<NDIAG, 512>>>(dgm0, d1rel, d1ext, Wp, bp);
    k_final<<<1, 1024>>>(Wfin, bfin, gfin, befin, out);
}

// round 17
// speedup vs baseline: 1.0741x; 1.0741x over previous
#include <cuda_runtime.h>
#include <cstdint>
#include <cfloat>

#define EPSB 1e-5f
constexpr int Lc  = 32;
constexpr int Ec  = 1024;
constexpr int Vc  = 2048;
constexpr int Fc  = 8;
constexpr int NT  = Lc * Ec;            // 32768
constexpr int D0c = 512, D1Rc = 129, D1Ec = 640;
constexpr int SIGc = 584;               // 8 + 64 + 512
constexpr int NDIAG = Lc * Fc * 2;      // 512
constexpr int GEMM_BLKS = NT / 128;     // 256
constexpr float DT = 1.0f / 51360.0f;   // arange(320)/(320*321/2)

typedef unsigned long long u64;

// packed fp32x2 helpers (Blackwell FFMA2 path — bit-exact fp32 per lane)
__device__ __forceinline__ u64 pk2(float lo, float hi) {
    u64 r;
    asm("mov.b64 %0, {%1, %2};" : "=l"(r) : "r"(__float_as_uint(lo)), "r"(__float_as_uint(hi)));
    return r;
}
__device__ __forceinline__ u64 ffma2(u64 a, u64 b, u64 c) {
    u64 d;
    asm("fma.rn.f32x2 %0, %1, %2, %3;" : "=l"(d) : "l"(a), "l"(b), "l"(c));
    return d;
}
__device__ __forceinline__ void upk2(u64 v, float& lo, float& hi) {
    unsigned int a, b;
    asm("mov.b64 {%0, %1}, %2;" : "=r"(a), "=r"(b) : "l"(v));
    lo = __uint_as_float(a); hi = __uint_as_float(b);
}

// ---------------- static device scratch (no allocations) ----------------
__device__ float g_Z1[(size_t)Fc * NT * 128];     // 128 MB pre-BN layer-1 out
__device__ float g_Z2[(size_t)Fc * NT * 128];     // 128 MB pre-BN layer-2 out
__device__ float g_part[(size_t)Fc * GEMM_BLKS * 128 * 2];
__device__ float g_stats[2];
__device__ float g_alpha[Fc * 128], g_beta[Fc * 128];
__device__ float g_sc1[Fc * 128], g_sh1[Fc * 128];
__device__ float g_sc2[Fc * 128], g_sh2[Fc * 128];
__device__ float g_zout[(size_t)Fc * NT];
__device__ float g_zpart[Fc * 128 * 2];
__device__ float g_osc[Fc], g_osh[Fc];
__device__ float g_fv[(size_t)Lc * Fc * Vc];      // 2 MB filtration values
__device__ float g_sig[(size_t)NDIAG * SIGc];     // signatures

// ---------------- 1) batch mean/var of eigenvalues ----------------
__global__ void k_eigstats(const float* __restrict__ x) {
    __shared__ float ss[1024], sq[1024];
    int tid = threadIdx.x;
    float s = 0.f, q = 0.f;
    for (int i = tid; i < NT; i += 1024) { float v = x[i]; s += v; q += v * v; }
    ss[tid] = s; sq[tid] = q; __syncthreads();
    for (int o = 512; o; o >>= 1) {
        if (tid < o) { ss[tid] += ss[tid + o]; sq[tid] += sq[tid + o]; }
        __syncthreads();
    }
    if (tid == 0) {
        float m = ss[0] / (float)NT;
        g_stats[0] = m;
        g_stats[1] = sq[0] / (float)NT - m * m;
    }
}

// ---------------- 2) fold input Linear+BN into affine (bin cancels) ----------------
__global__ void k_l1prep(const float* __restrict__ Win, const float* __restrict__ gin,
                         const float* __restrict__ betain) {
    int tid = threadIdx.x;                     // f*128 + j
    float w   = Win[tid];
    float inv = rsqrtf(w * w * g_stats[1] + EPSB);
    float al  = w * inv * gin[tid];
    g_alpha[tid] = al;
    g_beta[tid]  = betain[tid] - g_stats[0] * al;
}

// ---------------- 3) hidden-layer SGEMM (f32x2 packed) + fused transform + stats ------
// layer 0: A[n][k] = relu(alpha[k]*x[n]+beta[k]);   dst g_Z1, weights Wh[f][0]
// layer 1: A[n][k] = relu(sc1[k]*Z1[n][k]+sh1[k]);  dst g_Z2, weights Wh[f][1]
__global__ void __launch_bounds__(256)
k_gemm(const float* __restrict__ x, const float* __restrict__ Wh,
       const float* __restrict__ bh, int layer)
{
    __shared__ __align__(16) float sA[16][132];
    __shared__ __align__(16) float sB[16][132];
    __shared__ float sX[128], sS[128], sH[128];

    int f = blockIdx.y, n0 = blockIdx.x * 128, tid = threadIdx.x;
    int tx = tid & 15, ty = tid >> 4;

    if (tid < 128) {
        if (layer == 0) {
            sS[tid] = g_alpha[f * 128 + tid];
            sH[tid] = g_beta [f * 128 + tid];
            sX[tid] = x[n0 + tid];
        } else {
            sS[tid] = g_sc1[f * 128 + tid];
            sH[tid] = g_sh1[f * 128 + tid];
        }
    }
    __syncthreads();

    const float* W    = Wh + (size_t)(f * 2 + layer) * (128 * 128); // [j][k]
    const float* Zsrc = g_Z1 + ((size_t)f * NT + n0) * 128;
    float*       Zdst = (layer == 0) ? g_Z1 : g_Z2;

    u64 acc2[8][4];
#pragma unroll
    for (int i = 0; i < 8; i++)
#pragma unroll
        for (int jp = 0; jp < 4; jp++) acc2[i][jp] = 0ull;

    for (int k0 = 0; k0 < 128; k0 += 16) {
#pragma unroll
        for (int it = 0; it < 8; it++) {
            int e = tid + it * 256;
            int r = e >> 4, kk = e & 15;
            float a;
            if (layer == 0) a = sS[k0 + kk] * sX[r] + sH[k0 + kk];
            else            a = sS[k0 + kk] * Zsrc[(size_t)r * 128 + k0 + kk] + sH[k0 + kk];
            sA[kk][r] = fmaxf(a, 0.f);
            sB[kk][r] = W[r * 128 + k0 + kk];
        }
        __syncthreads();
#pragma unroll
        for (int kk = 0; kk < 16; kk++) {
            float4 a0 = *(const float4*)&sA[kk][ty * 8];
            float4 a1 = *(const float4*)&sA[kk][ty * 8 + 4];
            float4 b0 = *(const float4*)&sB[kk][tx * 8];
            float4 b1 = *(const float4*)&sB[kk][tx * 8 + 4];
            u64 B2[4] = { pk2(b0.x, b0.y), pk2(b0.z, b0.w),
                          pk2(b1.x, b1.y), pk2(b1.z, b1.w) };
            float av[8] = {a0.x, a0.y, a0.z, a0.w, a1.x, a1.y, a1.z, a1.w};
#pragma unroll
            for (int i = 0; i < 8; i++) {
                u64 ad = pk2(av[i], av[i]);
#pragma unroll
                for (int jp = 0; jp < 4; jp++)
                    acc2[i][jp] = ffma2(ad, B2[jp], acc2[i][jp]);
            }
        }
        __syncthreads();
    }

    // epilogue: +bias, store, per-column stats partials (deterministic)
    float bb[8], cs[8], cq[8];
#pragma unroll
    for (int j = 0; j < 8; j++) {
        bb[j] = bh[(f * 2 + layer) * 128 + tx * 8 + j];
        cs[j] = 0.f; cq[j] = 0.f;
    }
#pragma unroll
    for (int i = 0; i < 8; i++) {
        float v[8];
#pragma unroll
        for (int jp = 0; jp < 4; jp++) upk2(acc2[i][jp], v[2 * jp], v[2 * jp + 1]);
#pragma unroll
        for (int j = 0; j < 8; j++) {
            v[j] += bb[j];
            cs[j] += v[j]; cq[j] += v[j] * v[j];
        }
        float* zr = Zdst + ((size_t)f * NT + n0 + ty * 8 + i) * 128 + tx * 8;
        *(float4*)(zr)     = make_float4(v[0], v[1], v[2], v[3]);
        *(float4*)(zr + 4) = make_float4(v[4], v[5], v[6], v[7]);
    }
#pragma unroll
    for (int j = 0; j < 8; j++) { sA[ty][tx * 8 + j] = cs[j]; sB[ty][tx * 8 + j] = cq[j]; }
    __syncthreads();
    if (tid < 128) {
        float s = 0.f, q = 0.f;
#pragma unroll
        for (int t = 0; t < 16; t++) { s += sA[t][tid]; q += sB[t][tid]; }
        size_t pi = ((size_t)f * gridDim.x + blockIdx.x) * 128 + tid;
        g_part[2 * pi]     = s;
        g_part[2 * pi + 1] = q;
    }
}

// ---------------- 4) reduce per-block stats -> BN scale/shift (1 warp per column) -----
__global__ void __launch_bounds__(1024)
k_colreduce(const float* __restrict__ gh, const float* __restrict__ beh, int layer) {
    int g = blockIdx.x * 32 + (threadIdx.x >> 5);   // column pair id 0..1023
    int lane = threadIdx.x & 31;
    int f = g >> 7, col = g & 127;
    float s = 0.f, q = 0.f;
    for (int b = lane; b < GEMM_BLKS; b += 32) {
        size_t pi = ((size_t)f * GEMM_BLKS + b) * 128 + col;
        s += g_part[2 * pi];
        q += g_part[2 * pi + 1];
    }
#pragma unroll
    for (int o = 16; o; o >>= 1) {
        s += __shfl_xor_sync(0xffffffffu, s, o);
        q += __shfl_xor_sync(0xffffffffu, q, o);
    }
    if (lane == 0) {
        float mean = s / (float)NT;
        float var  = q / (float)NT - mean * mean;
        float sc = gh[(f * 2 + layer) * 128 + col] * rsqrtf(var + EPSB);
        float sh = beh[(f * 2 + layer) * 128 + col] - mean * sc;
        if (layer == 0) { g_sc1[g] = sc; g_sh1[g] = sh; }
        else            { g_sc2[g] = sc; g_sh2[g] = sh; }
    }
}

// ---------------- 5) output layer: zout = relu(bn(Z2)) . Wout + bout; stats -----------
__global__ void __launch_bounds__(256)
k_outlayer(const float* __restrict__ Wout, const float* __restrict__ bout)
{
    __shared__ float sWo[128], sSc[128], sSh[128];
    __shared__ float rs[8], rq[8];
    int f = blockIdx.y, tid = threadIdx.x;
    int warp = tid >> 5, lane = tid & 31;
    if (tid < 128) {
        sWo[tid] = Wout[f * 128 + tid];
        sSc[tid] = g_sc2[f * 128 + tid];
        sSh[tid] = g_sh2[f * 128 + tid];
    }
    __syncthreads();
    float bo = bout[f];
    float bs = 0.f, bq = 0.f;
    int rbase = blockIdx.x * 256 + warp * 32;
    for (int r = 0; r < 32; r++) {
        const float* zr = g_Z2 + ((size_t)f * NT + rbase + r) * 128;
        float acc = 0.f;
#pragma unroll
        for (int q4 = 0; q4 < 4; q4++) {
            int j = lane + q4 * 32;
            acc = fmaf(fmaxf(fmaf(sSc[j], zr[j], sSh[j]), 0.f), sWo[j], acc);
        }
#pragma unroll
        for (int o = 16; o; o >>= 1) acc += __shfl_xor_sync(0xffffffffu, acc, o);
        if (lane == 0) {
            acc += bo;
            g_zout[(size_t)f * NT + rbase + r] = acc;
            bs += acc; bq += acc * acc;
        }
    }
    if (lane == 0) { rs[warp] = bs; rq[warp] = bq; }
    __syncthreads();
    if (tid == 0) {
        float s = 0.f, q = 0.f;
#pragma unroll
        for (int w = 0; w < 8; w++) { s += rs[w]; q += rq[w]; }
        g_zpart[((size_t)f * 128 + blockIdx.x) * 2]     = s;
        g_zpart[((size_t)f * 128 + blockIdx.x) * 2 + 1] = q;
    }
}

__global__ void k_zreduce(const float* __restrict__ gout, const float* __restrict__ beout) {
    int tid = threadIdx.x;                     // 256 = 8 f * 32 lanes
    int f = tid >> 5, lane = tid & 31;
    float s = 0.f, q = 0.f;
    for (int b = lane; b < 128; b += 32) {
        s += g_zpart[((size_t)f * 128 + b) * 2];
        q += g_zpart[((size_t)f * 128 + b) * 2 + 1];
    }
#pragma unroll
    for (int o = 16; o; o >>= 1) {
        s += __shfl_xor_sync(0xffffffffu, s, o);
        q += __shfl_xor_sync(0xffffffffu, q, o);
    }
    if (lane == 0) {
        float mean = s / (float)NT;
        float var  = q / (float)NT - mean * mean;
        float osc  = gout[f] * rsqrtf(var + EPSB);
        g_osc[f] = osc;
        g_osh[f] = beout[f] - mean * osc;
    }
}

// ---------------- 6) einsum: fv[l,f,v] = sum_e relu(bn(zout))[f,l,e] * evsq[l,e,v] ----
__global__ void __launch_bounds__(256)
k_einsum(const float* __restrict__ evsq)
{
    __shared__ float sev[8][1024];
    int l = blockIdx.y, tid = threadIdx.x;
    for (int i = tid; i < 8 * 1024; i += 256) {
        int f = i >> 10, e = i & 1023;
        float z = g_zout[(size_t)f * NT + (size_t)l * Ec + e];
        sev[f][e] = fmaxf(fmaf(g_osc[f], z, g_osh[f]), 0.f);
    }
    __syncthreads();
    int vh = blockIdx.x * 256 + tid;           // float2 index
    const float2* w2 = (const float2*)evsq + (size_t)l * Ec * (Vc / 2) + vh;
    float2 acc[8];
#pragma unroll
    for (int f = 0; f < 8; f++) { acc[f].x = 0.f; acc[f].y = 0.f; }
#pragma unroll 4
    for (int e = 0; e < Ec; e++) {
        float2 w = w2[(size_t)e * (Vc / 2)];
#pragma unroll
        for (int f = 0; f < 8; f++) {
            float sv = sev[f][e];
            acc[f].x = fmaf(sv, w.x, acc[f].x);
            acc[f].y = fmaf(sv, w.y, acc[f].y);
        }
    }
#pragma unroll
    for (int f = 0; f < 8; f++)
        ((float2*)g_fv)[(size_t)(l * Fc + f) * (Vc / 2) + vh] = acc[f];
}

// ---------------- 7) per-diagram: gather -> project -> sort -> level-3 signature ------
__global__ void __launch_bounds__(512)
k_diagram(const int* __restrict__ dgm0, const int* __restrict__ dgm1rel,
          const int* __restrict__ dgm1ext,
          const float* __restrict__ Wp, const float* __restrict__ bp)
{
    __shared__ float s_vals[640];
    __shared__ float s_srt[7][513];
    __shared__ float s_dx[319][8];

    int diag = blockIdx.x;
    int row = diag >> 1, which = diag & 1;
    int tid = threadIdx.x;
    const float* fvr = g_fv + (size_t)row * Vc;

    if (which == 0) {
        const int* i0 = dgm0 + (size_t)row * D0c;
        const int* ir = dgm1rel + (size_t)row * D1Rc;
        s_vals[tid] = fvr[i0[tid]];
        if (tid < 128) s_vals[512 + tid] = fvr[ir[128 - tid]];   // rel[1:][::-1]
    } else {
        const int* ie = dgm1ext + (size_t)row * D1Ec;
        for (int i = tid; i < 640; i += 512) s_vals[i] = fvr[ie[i]];
    }
    for (int i = tid; i < 7 * 192; i += 512) {                   // pad [320,512) with +inf
        int s = i / 192, p = 320 + (i % 192);
        s_srt[s][p] = FLT_MAX;
    }
    __syncthreads();
    for (int i = tid; i < 7 * 320; i += 512) {                   // Conv1d(1,7,k=2,s=2)
        int s = i / 320, p = i % 320;
        s_srt[s][p] = s_vals[2 * p] * Wp[2 * s] + s_vals[2 * p + 1] * Wp[2 * s + 1] + bp[s];
    }
    // bitonic sort ascending, 7 rows x 512 in parallel
    for (int k = 2; k <= 512; k <<= 1) {
        for (int j = k >> 1; j > 0; j >>= 1) {
            __syncthreads();
            int i = tid, ixj = i ^ j;
            if (ixj > i) {
                bool up = ((i & k) == 0);
#pragma unroll
                for (int r = 0; r < 7; r++) {
                    float x0 = s_srt[r][i], x1 = s_srt[r][ixj];
                    if ((x0 > x1) == up) { s_srt[r][i] = x1; s_srt[r][ixj] = x0; }
                }
            }
        }
    }
    __syncthreads();
    for (int i = tid; i < 319 * 8; i += 512) {                   // path deltas
        int p = i >> 3, d = i & 7;
        s_dx[p][d] = (d == 0) ? DT : (s_srt[d - 1][p + 1] - s_srt[d - 1][p]);
    }
    __syncthreads();

    // Chen scan: thread (a,b,c) owns s3[a,b,c], keeps private s1[a], s2[a,b]
    int a = tid >> 6, b = (tid >> 3) & 7, c = tid & 7;
    float ta = s_dx[0][a], tb = s_dx[0][b], tc = s_dx[0][c];
    float s1 = ta;
    float s2 = 0.5f * ta * tb;
    float s3 = s2 * tc * (1.0f / 3.0f);
    for (int p = 1; p < 319; p++) {
        ta = s_dx[p][a]; tb = s_dx[p][b]; tc = s_dx[p][c];
        float hb = 0.5f * tb;
        float u  = ta * hb;                    // t2[a,b]
        float t2bc = hb * tc;                  // t2[b,c]
        float v  = fmaf(u, 1.0f / 3.0f, s2);   // t3/tc + s2
        s3 = fmaf(tc, v, s3);
        s3 = fmaf(s1, t2bc, s3);
        s2 = fmaf(s1, tb, s2 + u);
        s1 += ta;
    }
    float* o = g_sig + (size_t)diag * SIGc;
    o[72 + tid] = s3;
    if (c == 0) o[8 + (tid >> 3)] = s2;
    if ((tid & 63) == 0) o[a] = s1;
}

// ---------------- 8) final linear + BN over 32 ----------------
__global__ void __launch_bounds__(1024)
k_final(const float* __restrict__ Wf, const float* __restrict__ bf,
        const float* __restrict__ gf, const float* __restrict__ btf,
        float* __restrict__ out)
{
    __shared__ float s_o[32];
    int w = threadIdx.x >> 5, lane = threadIdx.x & 31;
    const float* xr = g_sig + (size_t)w * 9344;
    float acc = 0.f;
    for (int k = lane; k < 9344; k += 32) acc = fmaf(xr[k], Wf[k], acc);
#pragma unroll
    for (int o = 16; o; o >>= 1) acc += __shfl_xor_sync(0xffffffffu, acc, o);
    if (lane == 0) s_o[w] = acc + bf[0];
    __syncthreads();
    if (threadIdx.x < 32) {
        float v = s_o[threadIdx.x];
        float s = v, q = v * v;
#pragma unroll
        for (int o = 16; o; o >>= 1) {
            s += __shfl_xor_sync(0xffffffffu, s, o);
            q += __shfl_xor_sync(0xffffffffu, q, o);
        }
        float m = s * (1.0f / 32.0f);
        float var = q * (1.0f / 32.0f) - m * m;
        out[threadIdx.x] = (v - m) * rsqrtf(var + EPSB) * gf[0] + btf[0];
    }
}

extern "C" void kernel_launch(void* const* d_in, const int* in_sizes, int n_in,
                              void* d_out, int out_size) {
    const float* eig   = (const float*)d_in[0];
    const float* evsq  = (const float*)d_in[1];
    const int*   dgm0  = (const int*)d_in[2];
    const int*   d1rel = (const int*)d_in[3];
    const int*   d1ext = (const int*)d_in[4];
    const float* Win   = (const float*)d_in[5];
    // d_in[6] = mlp_bin: cancels exactly inside the folded input-layer BN
    const float* gin   = (const float*)d_in[7];
    const float* bein  = (const float*)d_in[8];
    const float* Wh    = (const float*)d_in[9];
    const float* bh    = (const float*)d_in[10];
    const float* gh    = (const float*)d_in[11];
    const float* beh   = (const float*)d_in[12];
    const float* Wout  = (const float*)d_in[13];
    const float* bout  = (const float*)d_in[14];
    const float* gout  = (const float*)d_in[15];
    const float* beout = (const float*)d_in[16];
    const float* Wp    = (const float*)d_in[17];
    const float* bp    = (const float*)d_in[18];
    const float* Wfin  = (const float*)d_in[19];
    const float* bfin  = (const float*)d_in[20];
    const float* gfin  = (const float*)d_in[21];
    const float* befin = (const float*)d_in[22];
    float* out = (float*)d_out;

    k_eigstats<<<1, 1024>>>(eig);
    k_l1prep<<<1, 1024>>>(Win, gin, bein);
    dim3 gg(GEMM_BLKS, Fc);
    k_gemm<<<gg, 256>>>(eig, Wh, bh, 0);
    k_colreduce<<<32, 1024>>>(gh, beh, 0);
    k_gemm<<<gg, 256>>>(eig, Wh, bh, 1);
    k_colreduce<<<32, 1024>>>(gh, beh, 1);
    k_outlayer<<<dim3(128, Fc), 256>>>(Wout, bout);
    k_zreduce<<<1, 256>>>(gout, beout);
    k_einsum<<<dim3(4, Lc), 256>>>(evsq);
    k_diagram<<<NDIAG, 512>>>(dgm0, d1rel, d1ext, Wp, bp);
    k_final<<<1, 1024>>>(Wfin, bfin, gfin, befin, out);
}